// round 17
// baseline (speedup 1.0000x reference)
#include <cuda_runtime.h>
#include <cuda_fp16.h>
#include <cstdint>
#include <cstddef>
#include <math.h>

#define BB 2
#define TT 2048
#define CC 1024
#define HH 16
#define NROWS (BB*TT)   // 4096

// ---------------- scratch (static device allocations; no cudaMalloc) -------
__device__ __half g_qwh[CC*CC];
__device__ __half g_kwh[CC*CC];
__device__ __half g_vwh[CC*CC];
__device__ __half g_pwh[CC*CC];
__device__ __half g_xh[NROWS*CC];
__device__ __half g_yh[NROWS*CC];
__device__ __half g_qh[NROWS*CC];
__device__ __half g_kh[NROWS*CC];
__device__ __half g_vh[NROWS*CC];
__device__ __half g_vth[(size_t)BB*HH*64*TT];   // V^T: [(b*HH+h)*64+d][t]
__device__ float  g_ga[NROWS*HH];

// ---------------- helpers ----------------------------------------------------
__device__ __forceinline__ void cp_async16(uint32_t saddr, const void* g) {
    asm volatile("cp.async.cg.shared.global [%0], [%1], 16;\n" :: "r"(saddr), "l"(g));
}
__device__ __forceinline__ void cp_commit() {
    asm volatile("cp.async.commit_group;\n");
}
__device__ __forceinline__ void cp_wait0() {
    asm volatile("cp.async.wait_group 0;\n");
}
__device__ __forceinline__ void cp_wait1() {
    asm volatile("cp.async.wait_group 1;\n");
}
__device__ __forceinline__ void mma_fp16(float c[4], uint32_t a0, uint32_t a1,
                                         uint32_t a2, uint32_t a3,
                                         uint32_t b0, uint32_t b1) {
    asm volatile(
        "mma.sync.aligned.m16n8k16.row.col.f32.f16.f16.f32 "
        "{%0,%1,%2,%3}, {%4,%5,%6,%7}, {%8,%9}, {%0,%1,%2,%3};"
        : "+f"(c[0]), "+f"(c[1]), "+f"(c[2]), "+f"(c[3])
        : "r"(a0), "r"(a1), "r"(a2), "r"(a3), "r"(b0), "r"(b1));
}

// ---------------- 1) fuse mix -> fp16 weights; wi=3 cpw; wi=4 converts x ----
__global__ void fuse_kernel(const float* __restrict__ x,
                            const float* __restrict__ cq, const float* __restrict__ ck,
                            const float* __restrict__ cv, const float* __restrict__ cp,
                            const float* __restrict__ qm,
                            const float* __restrict__ km, const float* __restrict__ vm) {
    int row = blockIdx.x;
    int wi  = blockIdx.y;
    int c = threadIdx.x * 4;
    if (wi == 4) {
#pragma unroll
        for (int rr = 0; rr < 4; rr++) {
            size_t off = (size_t)(row*4 + rr)*CC + c;
            float4 v = *(const float4*)&x[off];
            __half2 h0 = __floats2half2_rn(v.x, v.y);
            __half2 h1 = __floats2half2_rn(v.z, v.w);
            uint2 r = {*(uint32_t*)&h0, *(uint32_t*)&h1};
            *(uint2*)&g_xh[off] = r;
        }
        return;
    }
    if (wi == 3) {
        float4 v = *(const float4*)&cp[row*CC + c];
        __half2 h0 = __floats2half2_rn(v.x, v.y);
        __half2 h1 = __floats2half2_rn(v.z, v.w);
        uint2 r = {*(uint32_t*)&h0, *(uint32_t*)&h1};
        *(uint2*)&g_pwh[row*CC + c] = r;
        return;
    }
    const float* W = (wi == 0) ? cq : (wi == 1) ? ck : cv;
    const float* M = (wi == 0) ? qm : (wi == 1) ? km : vm;
    __half* O      = (wi == 0) ? g_qwh : (wi == 1) ? g_kwh : g_vwh;
    int h = row >> 6, d = row & 63;
    float mx[16];
#pragma unroll
    for (int m = 0; m < 16; m++) mx[m] = M[h*16 + m];
    float4 s = {0.f, 0.f, 0.f, 0.f};
#pragma unroll
    for (int m = 0; m < 16; m++) {
        float4 w = *(const float4*)&W[(size_t)(m*64 + d)*CC + c];
        s.x += mx[m]*w.x; s.y += mx[m]*w.y;
        s.z += mx[m]*w.z; s.w += mx[m]*w.w;
    }
    __half2 h0 = __floats2half2_rn(s.x, s.y);
    __half2 h1 = __floats2half2_rn(s.z, s.w);
    uint2 r = {*(uint32_t*)&h0, *(uint32_t*)&h1};
    *(uint2*)&O[row*CC + c] = r;
}

// ---------------- 2) NT GEMM, fp16 m16n8k16, BK=32, 3-stage; output T -------
#define HST 40
#define HSTG (128*HST)
#define GEMM_SMEM (3*2*HSTG*2)

template <typename TO>
__global__ __launch_bounds__(256, 2) void gemm_fp16_kernel(
    const __half* __restrict__ A,
    const __half* __restrict__ B0, TO* __restrict__ C0,
    const __half* __restrict__ B1, TO* __restrict__ C1,
    const __half* __restrict__ B2, TO* __restrict__ C2,
    int K) {
    const __half* Bm = (blockIdx.z == 0) ? B0 : (blockIdx.z == 1) ? B1 : B2;
    TO*           Cm = (blockIdx.z == 0) ? C0 : (blockIdx.z == 1) ? C1 : C2;
    const int N = CC;

    extern __shared__ __half hsm[];
    __half* Asm = hsm;
    __half* Bsm = hsm + 3*HSTG;

    const int tid  = threadIdx.x;
    const int lane = tid & 31;
    const int warp = tid >> 5;
    const int wr = warp & 1;
    const int wc = warp >> 1;
    const int g  = lane >> 2;
    const int l4 = lane & 3;
    const int brow = blockIdx.x * 128, bcol = blockIdx.y * 128;

    const int lrow = tid >> 1;
    const int lch  = (tid & 1) * 16;
    const __half* Ab = A  + (size_t)(brow + lrow) * K + lch;
    const __half* Bb = Bm + (size_t)(bcol + lrow) * K + lch;
    const uint32_t Ad = (uint32_t)__cvta_generic_to_shared(Asm + lrow*HST + lch);
    const uint32_t Bd = (uint32_t)__cvta_generic_to_shared(Bsm + lrow*HST + lch);
    const uint32_t stageB = HSTG * 2;

    const int NIT = K / 32;

#pragma unroll
    for (int s = 0; s < 2; s++) {
        cp_async16(Ad + s*stageB,      Ab + s*32);
        cp_async16(Ad + s*stageB + 16, Ab + s*32 + 8);
        cp_async16(Bd + s*stageB,      Bb + s*32);
        cp_async16(Bd + s*stageB + 16, Bb + s*32 + 8);
        cp_commit();
    }

    float acc[4][4][4];
#pragma unroll
    for (int mi = 0; mi < 4; mi++)
#pragma unroll
        for (int ni = 0; ni < 4; ni++)
#pragma unroll
            for (int r = 0; r < 4; r++) acc[mi][ni][r] = 0.f;

    for (int it = 0; it < NIT; it++) {
        if (it + 1 < NIT) cp_wait1(); else cp_wait0();
        __syncthreads();
        if (it + 2 < NIT) {
            int s = (it + 2) % 3;
            cp_async16(Ad + s*stageB,      Ab + (it+2)*32);
            cp_async16(Ad + s*stageB + 16, Ab + (it+2)*32 + 8);
            cp_async16(Bd + s*stageB,      Bb + (it+2)*32);
            cp_async16(Bd + s*stageB + 16, Bb + (it+2)*32 + 8);
            cp_commit();
        }
        const uint32_t* Aw = (const uint32_t*)(Asm + (it % 3)*HSTG);
        const uint32_t* Bw = (const uint32_t*)(Bsm + (it % 3)*HSTG);
#pragma unroll
        for (int ks = 0; ks < 2; ks++) {
            const int k0w = ks*8;
            uint32_t bf[4][2];
#pragma unroll
            for (int ni = 0; ni < 4; ni++) {
                const uint32_t* bp = Bw + (wc*32 + ni*8 + g)*20 + k0w + l4;
                bf[ni][0] = bp[0];
                bf[ni][1] = bp[4];
            }
#pragma unroll
            for (int mi = 0; mi < 4; mi++) {
                const uint32_t* ap0 = Aw + (wr*64 + mi*16 + g)*20 + k0w + l4;
                const uint32_t* ap1 = ap0 + 8*20;
                uint32_t a0 = ap0[0];
                uint32_t a1 = ap1[0];
                uint32_t a2 = ap0[4];
                uint32_t a3 = ap1[4];
#pragma unroll
                for (int ni = 0; ni < 4; ni++)
                    mma_fp16(acc[mi][ni], a0, a1, a2, a3, bf[ni][0], bf[ni][1]);
            }
        }
    }

#pragma unroll
    for (int mi = 0; mi < 4; mi++) {
#pragma unroll
        for (int ni = 0; ni < 4; ni++) {
            int row0 = brow + wr*64 + mi*16 + g;
            int col  = bcol + wc*32 + ni*8 + 2*l4;
            if (sizeof(TO) == 4) {
                float2 w0 = {acc[mi][ni][0], acc[mi][ni][1]};
                float2 w1 = {acc[mi][ni][2], acc[mi][ni][3]};
                *(float2*)((float*)Cm + (size_t)row0 * N + col)       = w0;
                *(float2*)((float*)Cm + (size_t)(row0 + 8) * N + col) = w1;
            } else {
                __half2 w0 = __floats2half2_rn(acc[mi][ni][0], acc[mi][ni][1]);
                __half2 w1 = __floats2half2_rn(acc[mi][ni][2], acc[mi][ni][3]);
                *(__half2*)((__half*)Cm + (size_t)row0 * N + col)       = w0;
                *(__half2*)((__half*)Cm + (size_t)(row0 + 8) * N + col) = w1;
            }
        }
    }
}

// ---------------- 3) gates + RoPE + RMSNorm; ONE THREAD per (bt,h) ----------
// q additionally scaled by 0.125 (softmax scale folded in).
__global__ __launch_bounds__(256) void post_kernel(
    const float* __restrict__ x, const float* __restrict__ ve,
    const float* __restrict__ cosb, const float* __restrict__ sinb,
    const float* __restrict__ vgw, const float* __restrict__ agw) {
    int gid = blockIdx.x * blockDim.x + threadIdx.x;   // 0..NROWS*HH-1
    int h  = gid & 15;
    int bt = gid >> 4;
    int t  = bt % TT;
    size_t xbase = (size_t)bt * CC;
    const float* xp = x + xbase;

    float gv = 0.f, ga = 0.f;
    const float* vg = vgw + h*32;
    const float* ag = agw + h*12;
#pragma unroll
    for (int i = 0; i < 32; i += 4) {
        float4 xv = *(const float4*)(xp + i);
        float4 wv = *(const float4*)(vg + i);
        gv += xv.x*wv.x + xv.y*wv.y + xv.z*wv.z + xv.w*wv.w;
        if (i < 12) {
            float4 av = *(const float4*)(ag + i);
            ga += xv.x*av.x + xv.y*av.y + xv.z*av.z + xv.w*av.w;
        }
    }
    float gate_v = 2.f / (1.f + __expf(-gv));
    g_ga[(size_t)bt*HH + h] = 1.f / (1.f + __expf(-ga));

    size_t idx = xbase + h*64;

    // v += gate_v * ve
#pragma unroll
    for (int i = 0; i < 64; i += 8) {
        uint4 hv = *(const uint4*)(g_vh + idx + i);
        __half2* hp = (__half2*)&hv;
        float4 e0 = *(const float4*)(ve + idx + i);
        float4 e1 = *(const float4*)(ve + idx + i + 4);
        float2 a0 = __half22float2(hp[0]);
        float2 a1 = __half22float2(hp[1]);
        float2 a2 = __half22float2(hp[2]);
        float2 a3 = __half22float2(hp[3]);
        hp[0] = __floats2half2_rn(a0.x + gate_v*e0.x, a0.y + gate_v*e0.y);
        hp[1] = __floats2half2_rn(a1.x + gate_v*e0.z, a1.y + gate_v*e0.w);
        hp[2] = __floats2half2_rn(a2.x + gate_v*e1.x, a2.y + gate_v*e1.y);
        hp[3] = __floats2half2_rn(a3.x + gate_v*e1.z, a3.y + gate_v*e1.w);
        *(uint4*)(g_vh + idx + i) = hv;
    }

    const float* cp = cosb + t*32;
    const float* sp = sinb + t*32;

    // q: rope + rmsnorm, folded 0.125
    {
        uint4 lo[4], hi[4];
#pragma unroll
        for (int j = 0; j < 4; j++) {
            lo[j] = *(const uint4*)(g_qh + idx + j*8);
            hi[j] = *(const uint4*)(g_qh + idx + 32 + j*8);
        }
        float r1[32], r2[32];
        float ss = 0.f;
        const __half2* l2 = (const __half2*)lo;
        const __half2* h2 = (const __half2*)hi;
#pragma unroll
        for (int i = 0; i < 16; i++) {
            float2 a = __half22float2(l2[i]);
            float2 b = __half22float2(h2[i]);
            float c0 = cp[2*i], c1 = cp[2*i+1];
            float s0 = sp[2*i], s1 = sp[2*i+1];
            r1[2*i]   =  a.x*c0 + b.x*s0;
            r1[2*i+1] =  a.y*c1 + b.y*s1;
            r2[2*i]   = -a.x*s0 + b.x*c0;
            r2[2*i+1] = -a.y*s1 + b.y*c1;
            ss += r1[2*i]*r1[2*i] + r1[2*i+1]*r1[2*i+1]
                + r2[2*i]*r2[2*i] + r2[2*i+1]*r2[2*i+1];
        }
        float sc = rsqrtf(ss * (1.f/64.f) + 1e-6f) * 0.125f;
        uint4 olo[4], ohi[4];
        __half2* ol = (__half2*)olo;
        __half2* oh = (__half2*)ohi;
#pragma unroll
        for (int i = 0; i < 16; i++) {
            ol[i] = __floats2half2_rn(r1[2*i]*sc, r1[2*i+1]*sc);
            oh[i] = __floats2half2_rn(r2[2*i]*sc, r2[2*i+1]*sc);
        }
#pragma unroll
        for (int j = 0; j < 4; j++) {
            *(uint4*)(g_qh + idx + j*8)      = olo[j];
            *(uint4*)(g_qh + idx + 32 + j*8) = ohi[j];
        }
    }
    // k: rope + rmsnorm (no extra scale)
    {
        uint4 lo[4], hi[4];
#pragma unroll
        for (int j = 0; j < 4; j++) {
            lo[j] = *(const uint4*)(g_kh + idx + j*8);
            hi[j] = *(const uint4*)(g_kh + idx + 32 + j*8);
        }
        float r1[32], r2[32];
        float ss = 0.f;
        const __half2* l2 = (const __half2*)lo;
        const __half2* h2 = (const __half2*)hi;
#pragma unroll
        for (int i = 0; i < 16; i++) {
            float2 a = __half22float2(l2[i]);
            float2 b = __half22float2(h2[i]);
            float c0 = cp[2*i], c1 = cp[2*i+1];
            float s0 = sp[2*i], s1 = sp[2*i+1];
            r1[2*i]   =  a.x*c0 + b.x*s0;
            r1[2*i+1] =  a.y*c1 + b.y*s1;
            r2[2*i]   = -a.x*s0 + b.x*c0;
            r2[2*i+1] = -a.y*s1 + b.y*c1;
            ss += r1[2*i]*r1[2*i] + r1[2*i+1]*r1[2*i+1]
                + r2[2*i]*r2[2*i] + r2[2*i+1]*r2[2*i+1];
        }
        float sc = rsqrtf(ss * (1.f/64.f) + 1e-6f);
        uint4 olo[4], ohi[4];
        __half2* ol = (__half2*)olo;
        __half2* oh = (__half2*)ohi;
#pragma unroll
        for (int i = 0; i < 16; i++) {
            ol[i] = __floats2half2_rn(r1[2*i]*sc, r1[2*i+1]*sc);
            oh[i] = __floats2half2_rn(r2[2*i]*sc, r2[2*i+1]*sc);
        }
#pragma unroll
        for (int j = 0; j < 4; j++) {
            *(uint4*)(g_kh + idx + j*8)      = olo[j];
            *(uint4*)(g_kh + idx + 32 + j*8) = ohi[j];
        }
    }
}

// ---------------- 3b) transpose V -> V^T (fp16) ------------------------------
__global__ void vtrans_kernel() {
    __shared__ __half ts[64][65];
    const int tbk = blockIdx.x, h = blockIdx.y, b = blockIdx.z;
    const int tid = threadIdx.x;
    const size_t bT = (size_t)b*TT;
    const int t0 = tbk*64;
#pragma unroll
    for (int i = 0; i < 8; i++) {
        int w = tid + i*256;
        int t = w >> 5, dp = w & 31;
        uint32_t v = *(const uint32_t*)(g_vh + (bT + t0 + t)*CC + h*64 + 2*dp);
        __half2 hv = *(__half2*)&v;
        ts[2*dp][t]   = __low2half(hv);
        ts[2*dp+1][t] = __high2half(hv);
    }
    __syncthreads();
    const size_t vbase = ((size_t)(b*HH + h))*64;
#pragma unroll
    for (int i = 0; i < 8; i++) {
        int w = tid + i*256;
        int d = w >> 5, tp = w & 31;
        __half2 hv = __halves2half2(ts[d][2*tp], ts[d][2*tp+1]);
        *(uint32_t*)(g_vth + (vbase + d)*TT + t0 + 2*tp) = *(uint32_t*)&hv;
    }
}

// ---------------- 4) flash attention, fp16 mma, no-max softmax --------------
#define ASTH 72
#define ATTN_SMEM ((128*ASTH + 4*64*ASTH)*2)   // 55296 B

__global__ __launch_bounds__(256, 2) void attn_kernel(const int* __restrict__ wsp) {
    extern __shared__ __half ash[];
    __half* Qs = ash;
    __half* Ks = ash + 128*ASTH;
    __half* Vs = Ks  + 2*64*ASTH;

    const int qtb = (TT/128 - 1) - blockIdx.x;
    const int h = blockIdx.y, b = blockIdx.z;
    const int tid  = threadIdx.x;
    const int lane = tid & 31;
    const int w    = tid >> 5;
    const int g    = lane >> 2;
    const int l4   = lane & 3;
    const int q0   = qtb * 128;
    const int hoff = h*64;
    const size_t bT = (size_t)b*TT;
    const size_t vbase = ((size_t)(b*HH + h))*64;

    int wsv = wsp ? *wsp : -1;
    const bool use_w = (wsv >= 0) && (wsv < TT - 1);
    int jt0 = 0;
    if (use_w) {
        int lo = q0 - wsv - 63;
        if (lo > 0) jt0 = (lo + 63) >> 6;
    }
    const int jtmax = 2*qtb + 1;

    {
        int row = tid >> 1;
        int c0  = (tid & 1) * 4;
        const __half* src = g_qh + (bT + q0 + row)*CC + hoff;
        uint32_t dst = (uint32_t)__cvta_generic_to_shared(Qs + row*ASTH);
#pragma unroll
        for (int i = 0; i < 4; i++) cp_async16(dst + (c0 + i)*16, src + (c0 + i)*8);
        cp_commit();
    }
    {
        int r  = tid >> 2;
        int c0 = (tid & 3) * 2;
        int pos = jt0*64 + r;
        int sh  = (pos > 0) ? pos - 1 : 0;
        uint32_t kd = (uint32_t)__cvta_generic_to_shared(Ks + (jt0&1)*64*ASTH + r*ASTH);
        uint32_t vd = (uint32_t)__cvta_generic_to_shared(Vs + (jt0&1)*64*ASTH + r*ASTH);
        const __half* kp  = g_kh + (bT + pos)*CC + hoff;
        const __half* ksh = g_kh + (bT + sh)*CC + hoff;
        const __half* vp  = g_vth + (vbase + r)*TT + jt0*64;
#pragma unroll
        for (int i = 0; i < 2; i++) {
            int c = c0 + i;
            const __half* kb = (c < 4) ? kp : ksh;
            cp_async16(kd + c*16, kb + c*8);
            cp_async16(vd + c*16, vp + c*8);
        }
        cp_commit();
    }

    uint32_t qa[4][4];
    cp_wait1();
    __syncthreads();
    {
        const __half* q0p = Qs + (16*w + g)*ASTH;
        const __half* q1p = q0p + 8*ASTH;
#pragma unroll
        for (int ks = 0; ks < 4; ks++) {
            qa[ks][0] = *(const uint32_t*)(q0p + 16*ks + 2*l4);
            qa[ks][1] = *(const uint32_t*)(q1p + 16*ks + 2*l4);
            qa[ks][2] = *(const uint32_t*)(q0p + 16*ks + 2*l4 + 8);
            qa[ks][3] = *(const uint32_t*)(q1p + 16*ks + 2*l4 + 8);
        }
    }
    __syncwarp();

    float oacc[8][4];
#pragma unroll
    for (int nt = 0; nt < 8; nt++)
#pragma unroll
        for (int r = 0; r < 4; r++) oacc[nt][r] = 0.f;
    float li0 = 0.f, li1 = 0.f;

    const int wrmin = q0 + 16*w;
    const int wrmax = wrmin + 15;
    const int r0g   = wrmin + g;
    const int r1g   = r0g + 8;
    uint32_t* Pw0 = (uint32_t*)(Qs + (16*w + g)*ASTH);
    uint32_t* Pw1 = (uint32_t*)(Qs + (16*w + g + 8)*ASTH);

    for (int jt = jt0; jt <= jtmax; jt++) {
        const int kv0 = jt * 64;
        const int buf = jt & 1;
        cp_wait0();
        __syncthreads();

        if (jt < jtmax) {
            int r  = tid >> 2;
            int c0 = (tid & 3) * 2;
            int pos = kv0 + 64 + r;
            uint32_t kd = (uint32_t)__cvta_generic_to_shared(Ks + (buf^1)*64*ASTH + r*ASTH);
            uint32_t vd = (uint32_t)__cvta_generic_to_shared(Vs + (buf^1)*64*ASTH + r*ASTH);
            const __half* kp  = g_kh + (bT + pos)*CC + hoff;
            const __half* ksh = g_kh + (bT + pos - 1)*CC + hoff;
            const __half* vp  = g_vth + (vbase + r)*TT + kv0 + 64;
#pragma unroll
            for (int i = 0; i < 2; i++) {
                int c = c0 + i;
                const __half* kb = (c < 4) ? kp : ksh;
                cp_async16(kd + c*16, kb + c*8);
                cp_async16(vd + c*16, vp + c*8);
            }
            cp_commit();
        }

        bool dead = (kv0 > wrmax) || (use_w && (kv0 + 63 < wrmin - wsv));
        if (!dead) {
            const __half* Kb = Ks + buf*64*ASTH;
            const __half* Vb = Vs + buf*64*ASTH;

            float sacc[8][4];
#pragma unroll
            for (int nt = 0; nt < 8; nt++)
#pragma unroll
                for (int r = 0; r < 4; r++) sacc[nt][r] = 0.f;
#pragma unroll
            for (int ks = 0; ks < 4; ks++) {
#pragma unroll
                for (int nt = 0; nt < 8; nt++) {
                    const __half* kp2 = Kb + (8*nt + g)*ASTH + 16*ks + 2*l4;
                    uint32_t b0 = *(const uint32_t*)kp2;
                    uint32_t b1 = *(const uint32_t*)(kp2 + 8);
                    mma_fp16(sacc[nt], qa[ks][0], qa[ks][1], qa[ks][2], qa[ks][3], b0, b1);
                }
            }

            const bool full = (kv0 + 63 <= wrmin) &&
                              (!use_w || (wrmax - kv0 <= wsv));
            if (!full) {
#pragma unroll
                for (int nt = 0; nt < 8; nt++) {
                    int c0 = kv0 + 8*nt + 2*l4;
#pragma unroll
                    for (int r = 0; r < 4; r++) {
                        int qi = (r < 2) ? r0g : r1g;
                        int kj = c0 + (r & 1);
                        bool ok = (kj <= qi) && (!use_w || (qi - kj) <= wsv);
                        if (!ok) sacc[nt][r] = -1e30f;
                    }
                }
            }

            float sum0 = 0.f, sum1 = 0.f;
#pragma unroll
            for (int nt = 0; nt < 8; nt++) {
                float p0 = __expf(sacc[nt][0]);
                float p1 = __expf(sacc[nt][1]);
                float p2 = __expf(sacc[nt][2]);
                float p3 = __expf(sacc[nt][3]);
                sum0 += p0 + p1; sum1 += p2 + p3;
                __half2 hp0 = __floats2half2_rn(p0, p1);
                __half2 hp1 = __floats2half2_rn(p2, p3);
                Pw0[4*nt + l4] = *(uint32_t*)&hp0;
                Pw1[4*nt + l4] = *(uint32_t*)&hp1;
            }
            sum0 += __shfl_xor_sync(0xffffffffu, sum0, 1);
            sum0 += __shfl_xor_sync(0xffffffffu, sum0, 2);
            sum1 += __shfl_xor_sync(0xffffffffu, sum1, 1);
            sum1 += __shfl_xor_sync(0xffffffffu, sum1, 2);
            li0 += sum0;
            li1 += sum1;
            __syncwarp();

#pragma unroll
            for (int ks = 0; ks < 4; ks++) {
                uint32_t a0 = Pw0[8*ks + l4];
                uint32_t a1 = Pw1[8*ks + l4];
                uint32_t a2 = Pw0[8*ks + l4 + 4];
                uint32_t a3 = Pw1[8*ks + l4 + 4];
#pragma unroll
                for (int nt = 0; nt < 8; nt++) {
                    const __half* vp2 = Vb + (8*nt + g)*ASTH + 16*ks + 2*l4;
                    uint32_t b0 = *(const uint32_t*)vp2;
                    uint32_t b1 = *(const uint32_t*)(vp2 + 8);
                    mma_fp16(oacc[nt], a0, a1, a2, a3, b0, b1);
                }
            }
            __syncwarp();
        }
    }

    float ga0 = g_ga[(bT + r0g)*HH + h];
    float ga1 = g_ga[(bT + r1g)*HH + h];
    float inv0 = ga0 / li0;
    float inv1 = ga1 / li1;
    __half* y0 = g_yh + (bT + r0g)*CC + hoff;
    __half* y1 = g_yh + (bT + r1g)*CC + hoff;
#pragma unroll
    for (int nt = 0; nt < 8; nt++) {
        int c = 8*nt + 2*l4;
        __half2 w0 = __floats2half2_rn(oacc[nt][0]*inv0, oacc[nt][1]*inv0);
        __half2 w1 = __floats2half2_rn(oacc[nt][2]*inv1, oacc[nt][3]*inv1);
        *(__half2*)(y0 + c) = w0;
        *(__half2*)(y1 + c) = w1;
    }
}

// ---------------- launch ----------------------------------------------------
extern "C" void kernel_launch(void* const* d_in, const int* in_sizes, int n_in,
                              void* d_out, int out_size) {
    const float* x    = (const float*)d_in[0];
    const float* ve   = (const float*)d_in[1];
    const float* cosb = (const float*)d_in[2];
    const float* sinb = (const float*)d_in[3];
    const float* cqw  = (const float*)d_in[4];
    const float* ckw  = (const float*)d_in[5];
    const float* cvw  = (const float*)d_in[6];
    const float* cpw  = (const float*)d_in[7];
    const float* vgw  = (const float*)d_in[8];
    const float* agw  = (const float*)d_in[9];
    const float* qm   = (const float*)d_in[10];
    const float* km   = (const float*)d_in[11];
    const float* vm   = (const float*)d_in[12];
    const int*   wsp  = (n_in > 13) ? (const int*)d_in[13] : nullptr;
    float* out = (float*)d_out;

    __half *pqwh, *pkwh, *pvwh, *ppwh, *pxh, *pyh, *pqh, *pkh, *pvh;
    cudaGetSymbolAddress((void**)&pqwh, g_qwh);
    cudaGetSymbolAddress((void**)&pkwh, g_kwh);
    cudaGetSymbolAddress((void**)&pvwh, g_vwh);
    cudaGetSymbolAddress((void**)&ppwh, g_pwh);
    cudaGetSymbolAddress((void**)&pxh,  g_xh);
    cudaGetSymbolAddress((void**)&pyh,  g_yh);
    cudaGetSymbolAddress((void**)&pqh,  g_qh);
    cudaGetSymbolAddress((void**)&pkh,  g_kh);
    cudaGetSymbolAddress((void**)&pvh,  g_vh);

    // 1) fuse mixes + convert cpw + convert x (one launch)
    fuse_kernel<<<dim3(CC, 5), 256>>>(x, cqw, ckw, cvw, cpw, qm, km, vm);

    // 2) QKV projections (fp16 mma, fp16 output)
    cudaFuncSetAttribute(gemm_fp16_kernel<__half>,
                         cudaFuncAttributeMaxDynamicSharedMemorySize, GEMM_SMEM);
    cudaFuncSetAttribute(gemm_fp16_kernel<float>,
                         cudaFuncAttributeMaxDynamicSharedMemorySize, GEMM_SMEM);
    gemm_fp16_kernel<__half><<<dim3(NROWS/128, CC/128, 3), 256, GEMM_SMEM>>>(
        pxh, pqwh, pqh, pkwh, pkh, pvwh, pvh, CC);

    // 3) gates + rope + rmsnorm (thread per (bt,h); q pre-scaled by 1/8)
    post_kernel<<<NROWS*HH/256, 256>>>(x, ve, cosb, sinb, vgw, agw);

    // 3b) V transpose
    vtrans_kernel<<<dim3(TT/64, HH, BB), 256>>>();

    // 4) flash attention (fp16 mma, no-max softmax)
    cudaFuncSetAttribute(attn_kernel, cudaFuncAttributeMaxDynamicSharedMemorySize, ATTN_SMEM);
    attn_kernel<<<dim3(TT/128, HH, BB), 256, ATTN_SMEM>>>(wsp);

    // 5) output projection (fp16 mma, fp32 output)
    gemm_fp16_kernel<float><<<dim3(NROWS/128, CC/128, 1), 256, GEMM_SMEM>>>(
        pyh, ppwh, out, ppwh, out, ppwh, out, CC);
}